// round 7
// baseline (speedup 1.0000x reference)
#include <cuda_runtime.h>
#include <cuda_bf16.h>
#include <cstdint>

#define NN 100000
#define EE 1600000
#define DD 128
#define EPS 1e-5f

typedef unsigned short u16;
typedef unsigned int   u32;

// ---------------- device scratch ----------------
__device__ int g_cnt[NN];
__device__ int g_rowptr[NN + 1];
__device__ int g_csr[EE];
__device__ float g_h1[(size_t)NN * DD];
__device__ float g_h2[(size_t)NN * DD];
__device__ u16 g_WH[8 * DD * DD];            // [mat][n][k]  mat = 2*layer + (0=rel,1=root)
__device__ u16 g_WL[8 * DD * DD];
__device__ u16 g_ifH[(size_t)NN * DD], g_ifL[(size_t)NN * DD];
__device__ u16 g_pAH[(size_t)NN * DD], g_pAL[(size_t)NN * DD];
__device__ u16 g_pBH[(size_t)NN * DD], g_pBL[(size_t)NN * DD];
__device__ u16 g_agH[(size_t)NN * DD], g_agL[(size_t)NN * DD];

// ---------------- helpers ----------------
__device__ __forceinline__ u32 smem_u32(const void* p) {
    u32 a;
    asm("{ .reg .u64 t; cvta.to.shared.u64 t, %1; cvt.u32.u64 %0, t; }" : "=r"(a) : "l"(p));
    return a;
}

__device__ __forceinline__ void splitbf(float v, u16 &h, u16 &l) {
    __nv_bfloat16 hb = __float2bfloat16(v);
    float r = v - __bfloat162float(hb);
    __nv_bfloat16 lb = __float2bfloat16(r);
    h = *reinterpret_cast<u16*>(&hb);
    l = *reinterpret_cast<u16*>(&lb);
}

#define MMA(d, a, b0_, b1_)                                                     \
    asm volatile("mma.sync.aligned.m16n8k16.row.col.f32.bf16.bf16.f32 "         \
        "{%0,%1,%2,%3}, {%4,%5,%6,%7}, {%8,%9}, {%0,%1,%2,%3};"                 \
        : "+f"((d)[0]), "+f"((d)[1]), "+f"((d)[2]), "+f"((d)[3])                \
        : "r"((a)[0]), "r"((a)[1]), "r"((a)[2]), "r"((a)[3]), "r"(b0_), "r"(b1_))

#define CP16(dst, src)                                                          \
    asm volatile("cp.async.cg.shared.global [%0], [%1], 16;"                    \
                 :: "r"(dst), "l"(src) : "memory")
#define CP_COMMIT() asm volatile("cp.async.commit_group;" ::: "memory")
#define CP_WAIT0()  asm volatile("cp.async.wait_group 0;" ::: "memory")
#define CP_WAIT1()  asm volatile("cp.async.wait_group 1;" ::: "memory")

// ---------------- CSR build ----------------
__global__ void k_zero() {
    int i = blockIdx.x * blockDim.x + threadIdx.x;
    if (i < NN) g_cnt[i] = 0;
}
__global__ void k_count(const int* __restrict__ dst) {
    int e = blockIdx.x * blockDim.x + threadIdx.x;
    if (e < EE) atomicAdd(&g_cnt[dst[e]], 1);
}
__global__ void k_scan() {
    __shared__ int ss[1024];
    int tid = threadIdx.x;
    const int chunk = (NN + 1023) / 1024;
    int start = tid * chunk, stop = min(start + chunk, NN);
    int s = 0;
    for (int i = start; i < stop; i++) s += g_cnt[i];
    ss[tid] = s;
    __syncthreads();
    #pragma unroll
    for (int off = 1; off < 1024; off <<= 1) {
        int v = (tid >= off) ? ss[tid - off] : 0;
        __syncthreads();
        ss[tid] += v;
        __syncthreads();
    }
    int run = (tid == 0) ? 0 : ss[tid - 1];
    for (int i = start; i < stop; i++) {
        int c = g_cnt[i];
        g_rowptr[i] = run;
        g_cnt[i] = run;
        run += c;
    }
    if (tid == 0) g_rowptr[NN] = EE;
}
__global__ void k_fill(const int* __restrict__ src, const int* __restrict__ dst) {
    int e = blockIdx.x * blockDim.x + threadIdx.x;
    if (e < EE) {
        int pos = atomicAdd(&g_cnt[dst[e]], 1);
        g_csr[pos] = src[e];
    }
}

// ---------------- W transpose + bf16 split ----------------
__global__ void k_prep(const float* __restrict__ Wrel, const float* __restrict__ Wroot) {
    int mat = blockIdx.x;                 // 0..7
    int l = mat >> 1, which = mat & 1;
    const float* W = (which ? Wroot : Wrel) + (size_t)l * DD * DD;   // [k][n]
    u16* H  = g_WH + (size_t)mat * DD * DD;
    u16* Lo = g_WL + (size_t)mat * DD * DD;
    for (int idx = threadIdx.x; idx < DD * DD; idx += blockDim.x) {
        int k = idx >> 7, n = idx & 127;
        u16 h, lo;
        splitbf(W[idx], h, lo);
        H[n * DD + k] = h;
        Lo[n * DD + k] = lo;
    }
}

// ---------------- split in_feat to bf16 hi/lo ----------------
__global__ void k_split(const float* __restrict__ x, u16* __restrict__ xh, u16* __restrict__ xl) {
    int i = blockIdx.x * blockDim.x + threadIdx.x;      // pairs
    if (i < NN * DD / 2) {
        float2 v = ((const float2*)x)[i];
        u16 h0, l0, h1, l1;
        splitbf(v.x, h0, l0);
        splitbf(v.y, h1, l1);
        ((u32*)xh)[i] = (u32)h0 | ((u32)h1 << 16);
        ((u32*)xl)[i] = (u32)l0 | ((u32)l1 << 16);
    }
}

// ---------------- aggregation: warp per node, writes bf16 hi/lo ----------------
__global__ __launch_bounds__(256) void k_agg(const float* __restrict__ h,
                                             u16* __restrict__ agH, u16* __restrict__ agL) {
    int node = blockIdx.x * 8 + (threadIdx.x >> 5);
    if (node >= NN) return;
    int lane = threadIdx.x & 31;
    int beg = g_rowptr[node], end = g_rowptr[node + 1];
    float ax = 0.f, ay = 0.f, az = 0.f, aw = 0.f;
    int e = beg;
    for (; e + 4 <= end; e += 4) {
        int s0 = __ldg(&g_csr[e + 0]);
        int s1 = __ldg(&g_csr[e + 1]);
        int s2 = __ldg(&g_csr[e + 2]);
        int s3 = __ldg(&g_csr[e + 3]);
        float4 v0 = *(const float4*)(h + (size_t)s0 * DD + lane * 4);
        float4 v1 = *(const float4*)(h + (size_t)s1 * DD + lane * 4);
        float4 v2 = *(const float4*)(h + (size_t)s2 * DD + lane * 4);
        float4 v3 = *(const float4*)(h + (size_t)s3 * DD + lane * 4);
        ax += v0.x + v1.x + v2.x + v3.x;
        ay += v0.y + v1.y + v2.y + v3.y;
        az += v0.z + v1.z + v2.z + v3.z;
        aw += v0.w + v1.w + v2.w + v3.w;
    }
    for (; e < end; e++) {
        int s = __ldg(&g_csr[e]);
        float4 v = *(const float4*)(h + (size_t)s * DD + lane * 4);
        ax += v.x; ay += v.y; az += v.z; aw += v.w;
    }
    u16 hx, lx, hy, ly, hz, lz, hw, lw;
    splitbf(ax, hx, lx); splitbf(ay, hy, ly);
    splitbf(az, hz, lz); splitbf(aw, hw, lw);
    size_t off = (size_t)node * DD + lane * 4;
    *(uint2*)(agH + off) = make_uint2((u32)hx | ((u32)hy << 16), (u32)hz | ((u32)hw << 16));
    *(uint2*)(agL + off) = make_uint2((u32)lx | ((u32)ly << 16), (u32)lz | ((u32)lw << 16));
}

// ---------------- GEMM: bf16 mma.sync 3-term, 2-stage pipelined ----------------
// Smem: 2 stages x {AH, AL, BH, BL} x 128 rows x 48B (32B data + 16B pad) = 48KB.
// 16 chunks of k=16 (8 per matrix). Epilogue scratch overlays stage buffers.
// mode 0: +bias  1: +bias,relu,LN  2: +bias,+res,relu,LN
__device__ __forceinline__ void issue_chunk16(
    u32 smb, int buf, int c, int row0,
    const u16* __restrict__ aH, const u16* __restrict__ aL,
    const u16* __restrict__ bH, const u16* __restrict__ bL, int tid)
{
    const int kg = (c & 7) * 16;
    const int arr = tid >> 6;          // 0:AH 1:AL 2:BH 3:BL
    const bool isA = arr < 2;
    const u16* sp = (arr == 0) ? aH : (arr == 1) ? aL : (arr == 2) ? bH : bL;
    const u32 dbase = smb + (u32)buf * 24576u + (u32)arr * 6144u;
    const int lt = tid & 63;
    #pragma unroll
    for (int i = 0; i < 4; i++) {
        int seg = i * 64 + lt;              // 0..255
        int row = seg >> 1, q = seg & 1;
        int srow = row;
        if (isA) {
            int grow = row0 + row;
            srow = (grow < NN) ? grow : row0;   // clamp OOB rows (masked at store)
        }
        const char* src = (const char*)sp + ((size_t)srow * DD + kg + q * 8) * 2;
        u32 dst = dbase + row * 48 + q * 16;
        CP16(dst, src);
    }
}

__global__ __launch_bounds__(256, 2) void k_gemm(
    const u16* __restrict__ AH0, const u16* __restrict__ AL0,   // agg hi/lo
    const u16* __restrict__ AH1, const u16* __restrict__ AL1,   // root operand hi/lo
    const float* __restrict__ Hres,                             // residual fp32
    const u16* __restrict__ BH0, const u16* __restrict__ BL0,   // W_rel^T hi/lo
    const u16* __restrict__ BH1, const u16* __restrict__ BL1,   // W_root^T hi/lo
    const float* __restrict__ brel, const float* __restrict__ gamma,
    const float* __restrict__ beta,
    float* __restrict__ out, u16* __restrict__ outH, u16* __restrict__ outL,
    int mode)
{
    __shared__ u32 s_all[12288];           // 49152 bytes: 2 stages x 4 arrays x 1536 u32

    const int tid = threadIdx.x;
    const int lane = tid & 31, wid = tid >> 5;
    const int wm = wid & 3, wn = wid >> 2;
    const int g = lane >> 2, t = lane & 3;
    const int row0 = blockIdx.x * 128;
    const u32 smb = smem_u32(s_all);

    float acc[2][8][4];
    #pragma unroll
    for (int i = 0; i < 2; i++)
        #pragma unroll
        for (int j = 0; j < 8; j++)
            #pragma unroll
            for (int q = 0; q < 4; q++) acc[i][j][q] = 0.f;

    issue_chunk16(smb, 0, 0, row0, AH0, AL0, BH0, BL0, tid);
    CP_COMMIT();

    for (int c = 0; c < 16; c++) {
        if (c < 15) {
            int nc = c + 1, mm = nc >> 3;
            issue_chunk16(smb, nc & 1, nc, row0,
                          mm ? AH1 : AH0, mm ? AL1 : AL0,
                          mm ? BH1 : BH0, mm ? BL1 : BL0, tid);
            CP_COMMIT();
            CP_WAIT1();
        } else {
            CP_WAIT0();
        }
        __syncthreads();

        const u32* S = s_all + (c & 1) * 6144;
        u32 ah[2][4], al[2][4];
        #pragma unroll
        for (int i = 0; i < 2; i++) {
            int r0 = wm * 32 + i * 16 + g;
            ah[i][0] = S[r0 * 12 + t];
            ah[i][1] = S[(r0 + 8) * 12 + t];
            ah[i][2] = S[r0 * 12 + t + 4];
            ah[i][3] = S[(r0 + 8) * 12 + t + 4];
            al[i][0] = S[1536 + r0 * 12 + t];
            al[i][1] = S[1536 + (r0 + 8) * 12 + t];
            al[i][2] = S[1536 + r0 * 12 + t + 4];
            al[i][3] = S[1536 + (r0 + 8) * 12 + t + 4];
        }
        #pragma unroll
        for (int j = 0; j < 8; j++) {
            int n = wn * 64 + j * 8 + g;
            u32 b0 = S[3072 + n * 12 + t];
            u32 b1 = S[3072 + n * 12 + t + 4];
            MMA(acc[0][j], ah[0], b0, b1);
            MMA(acc[1][j], ah[1], b0, b1);
            MMA(acc[0][j], al[0], b0, b1);
            MMA(acc[1][j], al[1], b0, b1);
            u32 c0 = S[4608 + n * 12 + t];
            u32 c1 = S[4608 + n * 12 + t + 4];
            MMA(acc[0][j], ah[0], c0, c1);
            MMA(acc[1][j], ah[1], c0, c1);
        }
        __syncthreads();
    }

    // ---------------- epilogue (scratch overlays dead stage buffers) ----------------
    float*  s_par = (float*)s_all;               // 384 floats
    float2* s_red = (float2*)(s_all + 384);      // [2][128]

    for (int idx = tid; idx < 384; idx += 256)
        s_par[idx] = (idx < 128) ? brel[idx]
                   : (idx < 256) ? gamma[idx - 128]
                                 : beta[idx - 256];
    __syncthreads();

    if (mode != 0) {
        #pragma unroll
        for (int i = 0; i < 2; i++)
        #pragma unroll
        for (int p = 0; p < 2; p++) {
            int r = wm * 32 + i * 16 + p * 8 + g;
            int gr = row0 + r;
            float s1 = 0.f, s2 = 0.f;
            #pragma unroll
            for (int j = 0; j < 8; j++) {
                int cc = wn * 64 + j * 8 + 2 * t;
                float v0 = acc[i][j][2 * p]     + s_par[cc];
                float v1 = acc[i][j][2 * p + 1] + s_par[cc + 1];
                if (mode == 2 && gr < NN) {
                    float2 rv = *(const float2*)(Hres + (size_t)gr * DD + cc);
                    v0 += rv.x; v1 += rv.y;
                }
                v0 = fmaxf(v0, 0.f); v1 = fmaxf(v1, 0.f);
                acc[i][j][2 * p] = v0; acc[i][j][2 * p + 1] = v1;
                s1 += v0 + v1; s2 += v0 * v0 + v1 * v1;
            }
            s1 += __shfl_xor_sync(0xffffffffu, s1, 1);
            s1 += __shfl_xor_sync(0xffffffffu, s1, 2);
            s2 += __shfl_xor_sync(0xffffffffu, s2, 1);
            s2 += __shfl_xor_sync(0xffffffffu, s2, 2);
            if (t == 0) s_red[wn * 128 + r] = make_float2(s1, s2);
        }
        __syncthreads();
        #pragma unroll
        for (int i = 0; i < 2; i++)
        #pragma unroll
        for (int p = 0; p < 2; p++) {
            int r = wm * 32 + i * 16 + p * 8 + g;
            int gr = row0 + r;
            if (gr >= NN) continue;
            float2 ra = s_red[r], rb = s_red[128 + r];
            float s1 = ra.x + rb.x, s2 = ra.y + rb.y;
            const float inv = 1.f / (float)DD;
            float mu = s1 * inv;
            float var = fmaxf(s2 * inv - mu * mu, 0.f);
            float rs = rsqrtf(var + EPS);
            #pragma unroll
            for (int j = 0; j < 8; j++) {
                int cc = wn * 64 + j * 8 + 2 * t;
                float v0 = acc[i][j][2 * p], v1 = acc[i][j][2 * p + 1];
                float o0 = (v0 - mu) * rs * s_par[DD + cc]     + s_par[2 * DD + cc];
                float o1 = (v1 - mu) * rs * s_par[DD + cc + 1] + s_par[2 * DD + cc + 1];
                *(float2*)(out + (size_t)gr * DD + cc) = make_float2(o0, o1);
                u16 h0, l0, h1, l1;
                splitbf(o0, h0, l0);
                splitbf(o1, h1, l1);
                *(u32*)(outH + (size_t)gr * DD + cc) = (u32)h0 | ((u32)h1 << 16);
                *(u32*)(outL + (size_t)gr * DD + cc) = (u32)l0 | ((u32)l1 << 16);
            }
        }
    } else {
        #pragma unroll
        for (int i = 0; i < 2; i++)
        #pragma unroll
        for (int p = 0; p < 2; p++) {
            int r = wm * 32 + i * 16 + p * 8 + g;
            int gr = row0 + r;
            if (gr >= NN) continue;
            #pragma unroll
            for (int j = 0; j < 8; j++) {
                int cc = wn * 64 + j * 8 + 2 * t;
                float v0 = acc[i][j][2 * p]     + s_par[cc];
                float v1 = acc[i][j][2 * p + 1] + s_par[cc + 1];
                *(float2*)(out + (size_t)gr * DD + cc) = make_float2(v0, v1);
            }
        }
    }
}

// ---------------- launch ----------------
extern "C" void kernel_launch(void* const* d_in, const int* in_sizes, int n_in,
                              void* d_out, int out_size) {
    const float* in_feat = (const float*)d_in[0];
    const int*   ei      = (const int*)  d_in[1];
    const float* Wrel    = (const float*)d_in[2];
    const float* brel    = (const float*)d_in[3];
    const float* Wroot   = (const float*)d_in[4];
    const float* gamma   = (const float*)d_in[5];
    const float* beta    = (const float*)d_in[6];
    float*       out     = (float*)d_out;

    const int* src = ei;
    const int* dst = ei + EE;

    float *h1, *h2;
    u16 *WH, *WL, *ifH, *ifL, *pAH, *pAL, *pBH, *pBL, *agH, *agL;
    cudaGetSymbolAddress((void**)&h1,  g_h1);
    cudaGetSymbolAddress((void**)&h2,  g_h2);
    cudaGetSymbolAddress((void**)&WH,  g_WH);
    cudaGetSymbolAddress((void**)&WL,  g_WL);
    cudaGetSymbolAddress((void**)&ifH, g_ifH);
    cudaGetSymbolAddress((void**)&ifL, g_ifL);
    cudaGetSymbolAddress((void**)&pAH, g_pAH);
    cudaGetSymbolAddress((void**)&pAL, g_pAL);
    cudaGetSymbolAddress((void**)&pBH, g_pBH);
    cudaGetSymbolAddress((void**)&pBL, g_pBL);
    cudaGetSymbolAddress((void**)&agH, g_agH);
    cudaGetSymbolAddress((void**)&agL, g_agL);

    const int GB = (NN + 127) / 128;
    const int AB = (NN + 7) / 8;
    const int EB = (EE + 255) / 256;
    const int MM = DD * DD;

    k_prep <<<8, 256>>>(Wrel, Wroot);
    k_split<<<(NN * DD / 2 + 255) / 256, 256>>>(in_feat, ifH, ifL);
    k_zero <<<(NN + 255) / 256, 256>>>();
    k_count<<<EB, 256>>>(dst);
    k_scan <<<1, 1024>>>();
    k_fill <<<EB, 256>>>(src, dst);

    // layer 0: conv -> relu -> LN
    k_agg <<<AB, 256>>>(in_feat, agH, agL);
    k_gemm<<<GB, 256>>>(agH, agL, ifH, ifL, in_feat,
                        WH + 0*MM, WL + 0*MM, WH + 1*MM, WL + 1*MM,
                        brel, gamma, beta, h1, pAH, pAL, 1);
    // layer 1: conv -> +res -> relu -> LN
    k_agg <<<AB, 256>>>(h1, agH, agL);
    k_gemm<<<GB, 256>>>(agH, agL, pAH, pAL, h1,
                        WH + 2*MM, WL + 2*MM, WH + 3*MM, WL + 3*MM,
                        brel + DD, gamma, beta, h2, pBH, pBL, 2);
    // layer 2
    k_agg <<<AB, 256>>>(h2, agH, agL);
    k_gemm<<<GB, 256>>>(agH, agL, pBH, pBL, h2,
                        WH + 4*MM, WL + 4*MM, WH + 5*MM, WL + 5*MM,
                        brel + 2*DD, gamma, beta, h1, pAH, pAL, 2);
    // layer 3: conv only
    k_agg <<<AB, 256>>>(h1, agH, agL);
    k_gemm<<<GB, 256>>>(agH, agL, pAH, pAL, h1,
                        WH + 6*MM, WL + 6*MM, WH + 7*MM, WL + 7*MM,
                        brel + 3*DD, gamma, beta, out, pBH, pBL, 0);
}

// round 10
// speedup vs baseline: 1.0606x; 1.0606x over previous
#include <cuda_runtime.h>
#include <cuda_bf16.h>
#include <cstdint>

#define NN 100000
#define EE 1600000
#define DD 128
#define EPS 1e-5f

typedef unsigned short u16;
typedef unsigned int   u32;

// ---------------- device scratch ----------------
__device__ int g_cnt[NN];
__device__ int g_rowptr[NN + 1];
__device__ int g_csr[EE];
__device__ float g_h1[(size_t)NN * DD];
__device__ float g_h2[(size_t)NN * DD];
__device__ u16 g_WH[8 * DD * DD];            // [mat][n][k]  mat = 2*layer + (0=rel,1=root)
__device__ u16 g_WL[8 * DD * DD];
__device__ u16 g_ifH[(size_t)NN * DD], g_ifL[(size_t)NN * DD];
__device__ u16 g_pAH[(size_t)NN * DD], g_pAL[(size_t)NN * DD];
__device__ u16 g_pBH[(size_t)NN * DD], g_pBL[(size_t)NN * DD];
__device__ u16 g_agH[(size_t)NN * DD], g_agL[(size_t)NN * DD];

// ---------------- helpers ----------------
__device__ __forceinline__ u32 smem_u32(const void* p) {
    u32 a;
    asm("{ .reg .u64 t; cvta.to.shared.u64 t, %1; cvt.u32.u64 %0, t; }" : "=r"(a) : "l"(p));
    return a;
}

__device__ __forceinline__ void splitbf(float v, u16 &h, u16 &l) {
    __nv_bfloat16 hb = __float2bfloat16(v);
    float r = v - __bfloat162float(hb);
    __nv_bfloat16 lb = __float2bfloat16(r);
    h = *reinterpret_cast<u16*>(&hb);
    l = *reinterpret_cast<u16*>(&lb);
}

#define MMA(d, a, b0_, b1_)                                                     \
    asm volatile("mma.sync.aligned.m16n8k16.row.col.f32.bf16.bf16.f32 "         \
        "{%0,%1,%2,%3}, {%4,%5,%6,%7}, {%8,%9}, {%0,%1,%2,%3};"                 \
        : "+f"((d)[0]), "+f"((d)[1]), "+f"((d)[2]), "+f"((d)[3])                \
        : "r"((a)[0]), "r"((a)[1]), "r"((a)[2]), "r"((a)[3]), "r"(b0_), "r"(b1_))

#define LDSM4(r, addr)                                                          \
    asm volatile("ldmatrix.sync.aligned.m8n8.x4.shared.b16 {%0,%1,%2,%3}, [%4];"\
        : "=r"((r)[0]), "=r"((r)[1]), "=r"((r)[2]), "=r"((r)[3]) : "r"(addr))

#define CP16(dst, src)                                                          \
    asm volatile("cp.async.cg.shared.global [%0], [%1], 16;"                    \
                 :: "r"(dst), "l"(src) : "memory")
#define CP_COMMIT() asm volatile("cp.async.commit_group;" ::: "memory")
#define CP_WAIT0()  asm volatile("cp.async.wait_group 0;" ::: "memory")

// ---------------- CSR build ----------------
__global__ void k_zero() {
    int i = blockIdx.x * blockDim.x + threadIdx.x;
    if (i < NN) g_cnt[i] = 0;
}
__global__ void k_count(const int* __restrict__ dst) {
    int e = blockIdx.x * blockDim.x + threadIdx.x;
    if (e < EE) atomicAdd(&g_cnt[dst[e]], 1);
}
__global__ void k_scan() {
    __shared__ int ss[1024];
    int tid = threadIdx.x;
    const int chunk = (NN + 1023) / 1024;
    int start = tid * chunk, stop = min(start + chunk, NN);
    int s = 0;
    for (int i = start; i < stop; i++) s += g_cnt[i];
    ss[tid] = s;
    __syncthreads();
    #pragma unroll
    for (int off = 1; off < 1024; off <<= 1) {
        int v = (tid >= off) ? ss[tid - off] : 0;
        __syncthreads();
        ss[tid] += v;
        __syncthreads();
    }
    int run = (tid == 0) ? 0 : ss[tid - 1];
    for (int i = start; i < stop; i++) {
        int c = g_cnt[i];
        g_rowptr[i] = run;
        g_cnt[i] = run;
        run += c;
    }
    if (tid == 0) g_rowptr[NN] = EE;
}
__global__ void k_fill(const int* __restrict__ src, const int* __restrict__ dst) {
    int e = blockIdx.x * blockDim.x + threadIdx.x;
    if (e < EE) {
        int pos = atomicAdd(&g_cnt[dst[e]], 1);
        g_csr[pos] = src[e];
    }
}

// ---------------- W transpose + bf16 split ----------------
__global__ void k_prep(const float* __restrict__ Wrel, const float* __restrict__ Wroot) {
    int mat = blockIdx.x;                 // 0..7
    int l = mat >> 1, which = mat & 1;
    const float* W = (which ? Wroot : Wrel) + (size_t)l * DD * DD;   // [k][n]
    u16* H  = g_WH + (size_t)mat * DD * DD;
    u16* Lo = g_WL + (size_t)mat * DD * DD;
    for (int idx = threadIdx.x; idx < DD * DD; idx += blockDim.x) {
        int k = idx >> 7, n = idx & 127;
        u16 h, lo;
        splitbf(W[idx], h, lo);
        H[n * DD + k] = h;
        Lo[n * DD + k] = lo;
    }
}

// ---------------- split in_feat to bf16 hi/lo ----------------
__global__ void k_split(const float* __restrict__ x, u16* __restrict__ xh, u16* __restrict__ xl) {
    int i = blockIdx.x * blockDim.x + threadIdx.x;      // pairs
    if (i < NN * DD / 2) {
        float2 v = ((const float2*)x)[i];
        u16 h0, l0, h1, l1;
        splitbf(v.x, h0, l0);
        splitbf(v.y, h1, l1);
        ((u32*)xh)[i] = (u32)h0 | ((u32)h1 << 16);
        ((u32*)xl)[i] = (u32)l0 | ((u32)l1 << 16);
    }
}

// ---------------- aggregation: warp per node, writes bf16 hi/lo ----------------
__global__ __launch_bounds__(256) void k_agg(const float* __restrict__ h,
                                             u16* __restrict__ agH, u16* __restrict__ agL) {
    int node = blockIdx.x * 8 + (threadIdx.x >> 5);
    if (node >= NN) return;
    int lane = threadIdx.x & 31;
    int beg = g_rowptr[node], end = g_rowptr[node + 1];
    float ax = 0.f, ay = 0.f, az = 0.f, aw = 0.f;
    int e = beg;
    for (; e + 4 <= end; e += 4) {
        int s0 = __ldg(&g_csr[e + 0]);
        int s1 = __ldg(&g_csr[e + 1]);
        int s2 = __ldg(&g_csr[e + 2]);
        int s3 = __ldg(&g_csr[e + 3]);
        float4 v0 = *(const float4*)(h + (size_t)s0 * DD + lane * 4);
        float4 v1 = *(const float4*)(h + (size_t)s1 * DD + lane * 4);
        float4 v2 = *(const float4*)(h + (size_t)s2 * DD + lane * 4);
        float4 v3 = *(const float4*)(h + (size_t)s3 * DD + lane * 4);
        ax += v0.x + v1.x + v2.x + v3.x;
        ay += v0.y + v1.y + v2.y + v3.y;
        az += v0.z + v1.z + v2.z + v3.z;
        aw += v0.w + v1.w + v2.w + v3.w;
    }
    for (; e < end; e++) {
        int s = __ldg(&g_csr[e]);
        float4 v = *(const float4*)(h + (size_t)s * DD + lane * 4);
        ax += v.x; ay += v.y; az += v.z; aw += v.w;
    }
    u16 hx, lx, hy, ly, hz, lz, hw, lw;
    splitbf(ax, hx, lx); splitbf(ay, hy, ly);
    splitbf(az, hz, lz); splitbf(aw, hw, lw);
    size_t off = (size_t)node * DD + lane * 4;
    *(uint2*)(agH + off) = make_uint2((u32)hx | ((u32)hy << 16), (u32)hz | ((u32)hw << 16));
    *(uint2*)(agL + off) = make_uint2((u32)lx | ((u32)ly << 16), (u32)lz | ((u32)lw << 16));
}

// ---------------- GEMM: bf16 mma.sync 3-term + ldmatrix frag loads ----------------
// Static smem stage: {AH, AL, BH, BL} x 128 rows x 80B (64B data + 16B pad).
// OOB A-rows are clamped to row0 (their outputs are masked at store).
// mode 0: +bias  1: +bias,relu,LN  2: +bias,+res,relu,LN
__device__ __forceinline__ void issue_chunk(
    u32 smb, int c, int row0,
    const u16* __restrict__ aH, const u16* __restrict__ aL,
    const u16* __restrict__ bH, const u16* __restrict__ bL, int tid)
{
    const int kg = (c & 3) * 32;
    const int arr = tid >> 6;          // 0:AH 1:AL 2:BH 3:BL
    const bool isA = arr < 2;
    const u16* sp = (arr == 0) ? aH : (arr == 1) ? aL : (arr == 2) ? bH : bL;
    const u32 dbase = smb + arr * 10240;
    const int lt = tid & 63;
    #pragma unroll
    for (int i = 0; i < 8; i++) {
        int seg = i * 64 + lt;              // 0..511
        int row = seg >> 2, q = seg & 3;
        int srow = row;
        if (isA) {
            int grow = row0 + row;
            srow = (grow < NN) ? grow : row0;   // clamp OOB rows (masked at store)
        }
        const char* src = (const char*)sp + ((size_t)srow * DD + kg + q * 8) * 2;
        u32 dst = dbase + row * 80 + q * 16;
        CP16(dst, src);
    }
}

__global__ __launch_bounds__(256, 2) void k_gemm(
    const u16* __restrict__ AH0, const u16* __restrict__ AL0,   // agg hi/lo
    const u16* __restrict__ AH1, const u16* __restrict__ AL1,   // root operand hi/lo
    const float* __restrict__ Hres,                             // residual fp32
    const u16* __restrict__ BH0, const u16* __restrict__ BL0,   // W_rel^T hi/lo
    const u16* __restrict__ BH1, const u16* __restrict__ BL1,   // W_root^T hi/lo
    const float* __restrict__ brel, const float* __restrict__ gamma,
    const float* __restrict__ beta,
    float* __restrict__ out, u16* __restrict__ outH, u16* __restrict__ outL,
    int mode)
{
    __shared__ u32 s_stage[10240];         // 40960 bytes (4 arrays x 2560 u32)
    __shared__ float s_par[3 * DD];
    __shared__ float2 s_red[2][DD];

    const int tid = threadIdx.x;
    const int lane = tid & 31, wid = tid >> 5;
    const int wm = wid & 3, wn = wid >> 2;
    const int g = lane >> 2, t = lane & 3;
    const int row0 = blockIdx.x * 128;
    const u32 smb = smem_u32(s_stage);

    if (tid < DD) {
        s_par[tid]          = brel[tid];
        s_par[DD + tid]     = gamma[tid];
        s_par[2 * DD + tid] = beta[tid];
    }

    // ldmatrix per-lane addresses (row pitch 80B; k-halves at +0 / +16 bytes)
    // A x4 mats: (r0-7,k0-7),(r8-15,k0-7),(r0-7,k8-15),(r8-15,k8-15)
    const u32 aAddr = smb + (u32)(wm * 32 + ((lane >> 3) & 1) * 8 + (lane & 7)) * 80u
                    + (u32)(lane >> 4) * 16u;
    // B x4 mats (j-pair): (j0,k0-7),(j0,k8-15),(j1,k0-7),(j1,k8-15)
    const u32 bAddr = smb + 20480u
                    + (u32)(wn * 64 + (lane >> 4) * 8 + (lane & 7)) * 80u
                    + (u32)((lane >> 3) & 1) * 16u;

    float acc[2][8][4];
    #pragma unroll
    for (int i = 0; i < 2; i++)
        #pragma unroll
        for (int j = 0; j < 8; j++)
            #pragma unroll
            for (int q = 0; q < 4; q++) acc[i][j][q] = 0.f;

    for (int c = 0; c < 8; c++) {
        const int mm = c >> 2;
        issue_chunk(smb, c, row0,
                    mm ? AH1 : AH0, mm ? AL1 : AL0,
                    mm ? BH1 : BH0, mm ? BL1 : BL0, tid);
        CP_COMMIT();
        CP_WAIT0();
        __syncthreads();

        #pragma unroll
        for (int s = 0; s < 2; s++) {
            const u32 sa = (u32)s * 32u;
            u32 ah[2][4], al[2][4];
            LDSM4(ah[0], aAddr + sa);
            LDSM4(ah[1], aAddr + 1280u + sa);           // +16 rows
            LDSM4(al[0], aAddr + 10240u + sa);
            LDSM4(al[1], aAddr + 10240u + 1280u + sa);
            #pragma unroll
            for (int p = 0; p < 4; p++) {               // j-pairs
                u32 bh[4], bl[4];
                LDSM4(bh, bAddr + (u32)p * 1280u + sa);
                LDSM4(bl, bAddr + 10240u + (u32)p * 1280u + sa);
                const int j0 = 2 * p, j1 = 2 * p + 1;
                MMA(acc[0][j0], ah[0], bh[0], bh[1]);
                MMA(acc[1][j0], ah[1], bh[0], bh[1]);
                MMA(acc[0][j0], al[0], bh[0], bh[1]);
                MMA(acc[1][j0], al[1], bh[0], bh[1]);
                MMA(acc[0][j0], ah[0], bl[0], bl[1]);
                MMA(acc[1][j0], ah[1], bl[0], bl[1]);
                MMA(acc[0][j1], ah[0], bh[2], bh[3]);
                MMA(acc[1][j1], ah[1], bh[2], bh[3]);
                MMA(acc[0][j1], al[0], bh[2], bh[3]);
                MMA(acc[1][j1], al[1], bh[2], bh[3]);
                MMA(acc[0][j1], ah[0], bl[2], bl[3]);
                MMA(acc[1][j1], ah[1], bl[2], bl[3]);
            }
        }
        __syncthreads();
    }

    // ---------------- epilogue ----------------
    if (mode != 0) {
        #pragma unroll
        for (int i = 0; i < 2; i++)
        #pragma unroll
        for (int p = 0; p < 2; p++) {
            int r = wm * 32 + i * 16 + p * 8 + g;
            int gr = row0 + r;
            float s1 = 0.f, s2 = 0.f;
            #pragma unroll
            for (int j = 0; j < 8; j++) {
                int cc = wn * 64 + j * 8 + 2 * t;
                float v0 = acc[i][j][2 * p]     + s_par[cc];
                float v1 = acc[i][j][2 * p + 1] + s_par[cc + 1];
                if (mode == 2 && gr < NN) {
                    float2 rv = *(const float2*)(Hres + (size_t)gr * DD + cc);
                    v0 += rv.x; v1 += rv.y;
                }
                v0 = fmaxf(v0, 0.f); v1 = fmaxf(v1, 0.f);
                acc[i][j][2 * p] = v0; acc[i][j][2 * p + 1] = v1;
                s1 += v0 + v1; s2 += v0 * v0 + v1 * v1;
            }
            s1 += __shfl_xor_sync(0xffffffffu, s1, 1);
            s1 += __shfl_xor_sync(0xffffffffu, s1, 2);
            s2 += __shfl_xor_sync(0xffffffffu, s2, 1);
            s2 += __shfl_xor_sync(0xffffffffu, s2, 2);
            if (t == 0) s_red[wn][r] = make_float2(s1, s2);
        }
        __syncthreads();
        #pragma unroll
        for (int i = 0; i < 2; i++)
        #pragma unroll
        for (int p = 0; p < 2; p++) {
            int r = wm * 32 + i * 16 + p * 8 + g;
            int gr = row0 + r;
            if (gr >= NN) continue;
            float2 ra = s_red[0][r], rb = s_red[1][r];
            float s1 = ra.x + rb.x, s2 = ra.y + rb.y;
            const float inv = 1.f / (float)DD;
            float mu = s1 * inv;
            float var = fmaxf(s2 * inv - mu * mu, 0.f);
            float rs = rsqrtf(var + EPS);
            #pragma unroll
            for (int j = 0; j < 8; j++) {
                int cc = wn * 64 + j * 8 + 2 * t;
                float v0 = acc[i][j][2 * p], v1 = acc[i][j][2 * p + 1];
                float o0 = (v0 - mu) * rs * s_par[DD + cc]     + s_par[2 * DD + cc];
                float o1 = (v1 - mu) * rs * s_par[DD + cc + 1] + s_par[2 * DD + cc + 1];
                *(float2*)(out + (size_t)gr * DD + cc) = make_float2(o0, o1);
                u16 h0, l0, h1, l1;
                splitbf(o0, h0, l0);
                splitbf(o1, h1, l1);
                *(u32*)(outH + (size_t)gr * DD + cc) = (u32)h0 | ((u32)h1 << 16);
                *(u32*)(outL + (size_t)gr * DD + cc) = (u32)l0 | ((u32)l1 << 16);
            }
        }
    } else {
        __syncthreads();
        #pragma unroll
        for (int i = 0; i < 2; i++)
        #pragma unroll
        for (int p = 0; p < 2; p++) {
            int r = wm * 32 + i * 16 + p * 8 + g;
            int gr = row0 + r;
            if (gr >= NN) continue;
            #pragma unroll
            for (int j = 0; j < 8; j++) {
                int cc = wn * 64 + j * 8 + 2 * t;
                float v0 = acc[i][j][2 * p]     + s_par[cc];
                float v1 = acc[i][j][2 * p + 1] + s_par[cc + 1];
                *(float2*)(out + (size_t)gr * DD + cc) = make_float2(v0, v1);
            }
        }
    }
}

// ---------------- launch ----------------
extern "C" void kernel_launch(void* const* d_in, const int* in_sizes, int n_in,
                              void* d_out, int out_size) {
    const float* in_feat = (const float*)d_in[0];
    const int*   ei      = (const int*)  d_in[1];
    const float* Wrel    = (const float*)d_in[2];
    const float* brel    = (const float*)d_in[3];
    const float* Wroot   = (const float*)d_in[4];
    const float* gamma   = (const float*)d_in[5];
    const float* beta    = (const float*)d_in[6];
    float*       out     = (float*)d_out;

    const int* src = ei;
    const int* dst = ei + EE;

    float *h1, *h2;
    u16 *WH, *WL, *ifH, *ifL, *pAH, *pAL, *pBH, *pBL, *agH, *agL;
    cudaGetSymbolAddress((void**)&h1,  g_h1);
    cudaGetSymbolAddress((void**)&h2,  g_h2);
    cudaGetSymbolAddress((void**)&WH,  g_WH);
    cudaGetSymbolAddress((void**)&WL,  g_WL);
    cudaGetSymbolAddress((void**)&ifH, g_ifH);
    cudaGetSymbolAddress((void**)&ifL, g_ifL);
    cudaGetSymbolAddress((void**)&pAH, g_pAH);
    cudaGetSymbolAddress((void**)&pAL, g_pAL);
    cudaGetSymbolAddress((void**)&pBH, g_pBH);
    cudaGetSymbolAddress((void**)&pBL, g_pBL);
    cudaGetSymbolAddress((void**)&agH, g_agH);
    cudaGetSymbolAddress((void**)&agL, g_agL);

    const int GB = (NN + 127) / 128;
    const int AB = (NN + 7) / 8;
    const int EB = (EE + 255) / 256;
    const int MM = DD * DD;

    k_prep <<<8, 256>>>(Wrel, Wroot);
    k_split<<<(NN * DD / 2 + 255) / 256, 256>>>(in_feat, ifH, ifL);
    k_zero <<<(NN + 255) / 256, 256>>>();
    k_count<<<EB, 256>>>(dst);
    k_scan <<<1, 1024>>>();
    k_fill <<<EB, 256>>>(src, dst);

    // layer 0: conv -> relu -> LN
    k_agg <<<AB, 256>>>(in_feat, agH, agL);
    k_gemm<<<GB, 256>>>(agH, agL, ifH, ifL, in_feat,
                        WH + 0*MM, WL + 0*MM, WH + 1*MM, WL + 1*MM,
                        brel, gamma, beta, h1, pAH, pAL, 1);
    // layer 1: conv -> +res -> relu -> LN
    k_agg <<<AB, 256>>>(h1, agH, agL);
    k_gemm<<<GB, 256>>>(agH, agL, pAH, pAL, h1,
                        WH + 2*MM, WL + 2*MM, WH + 3*MM, WL + 3*MM,
                        brel + DD, gamma, beta, h2, pBH, pBL, 2);
    // layer 2
    k_agg <<<AB, 256>>>(h2, agH, agL);
    k_gemm<<<GB, 256>>>(agH, agL, pBH, pBL, h2,
                        WH + 4*MM, WL + 4*MM, WH + 5*MM, WL + 5*MM,
                        brel + 2*DD, gamma, beta, h1, pAH, pAL, 2);
    // layer 3: conv only
    k_agg <<<AB, 256>>>(h1, agH, agL);
    k_gemm<<<GB, 256>>>(agH, agL, pAH, pAL, h1,
                        WH + 6*MM, WL + 6*MM, WH + 7*MM, WL + 7*MM,
                        brel + 3*DD, gamma, beta, out, pBH, pBL, 0);
}